// round 15
// baseline (speedup 1.0000x reference)
#include <cuda_runtime.h>
#include <math.h>
#include <stdint.h>

// Scratch (no allocations). Zero-initialized; last block resets for replay.
static __device__ double g_slots[32 * 32];
static __device__ unsigned int g_count;

#define LOG2_1P1 0.13750352374993502f   // log2(1.1)
#define BIGC     1.099511627776e12f     // 2^40 (exact power of two)

#define ROWS    512                      // rows per pipeline stage (divides 2^22)
#define THREADS 64                       // 8 rows/thread/iter
#define STAGES  2

__device__ __forceinline__ float ex2f(float x) {
    float r; asm("ex2.approx.f32 %0, %1;" : "=f"(r) : "f"(x)); return r;
}
__device__ __forceinline__ float rcpf(float x) {
    float r; asm("rcp.approx.f32 %0, %1;" : "=f"(r) : "f"(x)); return r;
}
// sat((x - ti)*2^40) == [x >= ti] (exact except measure-zero equality)
__device__ __forceinline__ float stepc(float x, float neg_tiB) {
    return __saturatef(fmaf(x, BIGC, neg_tiB));
}

// total weight (1 + w_mid), predicate-free closed form (exact, rel_err 0.0):
//   min(sat(t*inv_a), sat(c2 - t*inv_cb)) + min(2^(1 - t/d), 1) + [p<0]
__device__ __forceinline__ float wmid1(float p, float t,
                                       float inv_a, float inv_cb, float c2,
                                       float inv_d) {
    float u = __saturatef(t * inv_a);
    float v = __saturatef(fmaf(t, -inv_cb, c2));
    float wlow = fminf(u, v);
    float e2 = ex2f(fmaf(t, -inv_d, 1.0f));
    float pneg = __saturatef(p * -BIGC);
    return wlow + fminf(e2, 1.0f) + pneg;
}

__device__ __forceinline__ float row_loss(float ph, float th,
                                          float pc, float tc,
                                          float pn, float tn,
                                          int ot) {
    float sp, st, dd, wcls, W, s;

    // ---- head: thr {150,500,1000,1800,2600}, a=80 b=1500 c=1750 d=2000
    sp = stepc(ph, -150.f*BIGC) + stepc(ph, -500.f*BIGC) + stepc(ph, -1000.f*BIGC)
       + stepc(ph, -1800.f*BIGC) + stepc(ph, -2600.f*BIGC);
    st = stepc(th, -150.f*BIGC) + stepc(th, -500.f*BIGC) + stepc(th, -1000.f*BIGC)
       + stepc(th, -1800.f*BIGC) + stepc(th, -2600.f*BIGC);
    dd = sp - st;
    wcls = ex2f(fabsf(dd) * LOG2_1P1);
    W = wmid1(ph, th, 1.0f/80.f, 1.0f/250.f, 7.0f, 1.0f/2000.f);
    s = fabsf(ph - th) * (wcls * W);

    // ---- chest: thr {22,35,45,55,65}*cs == x/cs vs fixed thr; a=10 b=75 c=85 d=100
    float cs = fmaf((float)ot, 0.1f, 0.8f);
    float ics = rcpf(cs);
    float pcs = pc * ics, tcs = tc * ics;
    sp = stepc(pcs, -22.f*BIGC) + stepc(pcs, -35.f*BIGC) + stepc(pcs, -45.f*BIGC)
       + stepc(pcs, -55.f*BIGC) + stepc(pcs, -65.f*BIGC);
    st = stepc(tcs, -22.f*BIGC) + stepc(tcs, -35.f*BIGC) + stepc(tcs, -45.f*BIGC)
       + stepc(tcs, -55.f*BIGC) + stepc(tcs, -65.f*BIGC);
    dd = sp - st;
    wcls = ex2f(fabsf(dd) * LOG2_1P1);
    W = wmid1(pc, tc, 1.0f/10.f, 1.0f/10.f, 8.5f, 1.0f/100.f);
    s = fmaf(fabsf(pc - tc), wcls * W, s);

    // ---- neck: thr {0.2,0.5,1.0,1.5,2.0}, a=0.15 b=1.5 c=1.7 d=1.9
    sp = stepc(pn, -0.2f*BIGC) + stepc(pn, -0.5f*BIGC) + stepc(pn, -1.0f*BIGC)
       + stepc(pn, -1.5f*BIGC) + stepc(pn, -2.0f*BIGC);
    st = stepc(tn, -0.2f*BIGC) + stepc(tn, -0.5f*BIGC) + stepc(tn, -1.0f*BIGC)
       + stepc(tn, -1.5f*BIGC) + stepc(tn, -2.0f*BIGC);
    dd = sp - st;
    wcls = ex2f(fabsf(dd) * LOG2_1P1);
    W = wmid1(pn, tn, 1.0f/0.15f, 5.0f, 8.5f, 1.0f/1.9f);
    s = fmaf(fabsf(pn - tn), wcls * W, s);

    return s;
}

__device__ __forceinline__ void bulk_cp(unsigned dst, const char* src,
                                        unsigned bytes, unsigned mb) {
    asm volatile(
        "cp.async.bulk.shared::cta.global.mbarrier::complete_tx::bytes "
        "[%0], [%1], %2, [%3];"
        :: "r"(dst), "l"(src), "r"(bytes), "r"(mb) : "memory");
}
__device__ __forceinline__ void mbar_expect(unsigned mb, unsigned bytes) {
    asm volatile("mbarrier.arrive.expect_tx.shared.b64 _, [%0], %1;"
                 :: "r"(mb), "r"(bytes) : "memory");
}
__device__ __forceinline__ void mbar_wait(unsigned mb, unsigned phase) {
    asm volatile(
        "{\n\t"
        ".reg .pred P;\n\t"
        "W%=:\n\t"
        "mbarrier.try_wait.parity.acquire.cta.shared::cta.b64 P, [%0], %1, 0x989680;\n\t"
        "@!P bra W%=;\n\t"
        "}"
        :: "r"(mb), "r"(phase) : "memory");
}

// 2-stage bulk-copy ring, 64-thread CTAs (7/SM), 8 rows/thread/iter.
// Generous register budget (64K / (7*64) ~ 146/thread) lets the 8-row
// live set stay in registers; per-row sync/loop overhead is halved vs 4-row.
__global__ void __launch_bounds__(THREADS)
k_loss(const char* __restrict__ pred_b, const char* __restrict__ true_b,
       const char* __restrict__ ot_b,
       const float* __restrict__ pred, const float* __restrict__ truep,
       const int* __restrict__ ot,
       float* __restrict__ out,
       long long NST, long long n_tail, long long B, unsigned int n_blocks) {
    __shared__ alignas(16) float sh_p[STAGES][ROWS * 3];
    __shared__ alignas(16) float sh_t[STAGES][ROWS * 3];
    __shared__ alignas(16) int   sh_o[STAGES][ROWS];
    __shared__ alignas(8) unsigned long long mbar_store[STAGES];
    __shared__ float shred[2];

    unsigned mb[STAGES];
    #pragma unroll
    for (int i = 0; i < STAGES; i++)
        mb[i] = (unsigned)__cvta_generic_to_shared(&mbar_store[i]);

    if (threadIdx.x == 0) {
        #pragma unroll
        for (int i = 0; i < STAGES; i++)
            asm volatile("mbarrier.init.shared.b64 [%0], 1;" :: "r"(mb[i]) : "memory");
    }
    __syncthreads();

    const long long G = gridDim.x;
    long long s0 = blockIdx.x;
    const long long niter = (s0 < NST) ? ((NST - 1 - s0) / G + 1) : 0;

    const unsigned PT_BYTES = ROWS * 12u;                 // 6144
    const unsigned OT_BYTES = ROWS * 4u;                  // 2048
    const unsigned ST_BYTES = 2u * PT_BYTES + OT_BYTES;   // 14336

    // prologue: issue fills for stages s0, s0+G into bufs 0..1
    if (threadIdx.x == 0) {
        #pragma unroll
        for (int k = 0; k < STAGES; k++) {
            if (k < niter) {
                long long st_ = s0 + (long long)k * G;
                mbar_expect(mb[k], ST_BYTES);
                bulk_cp((unsigned)__cvta_generic_to_shared(&sh_p[k][0]),
                        pred_b + st_ * (long long)PT_BYTES, PT_BYTES, mb[k]);
                bulk_cp((unsigned)__cvta_generic_to_shared(&sh_t[k][0]),
                        true_b + st_ * (long long)PT_BYTES, PT_BYTES, mb[k]);
                bulk_cp((unsigned)__cvta_generic_to_shared(&sh_o[k][0]),
                        ot_b + st_ * (long long)OT_BYTES, OT_BYTES, mb[k]);
            }
        }
    }

    float acc0 = 0.0f, acc1 = 0.0f, acc2 = 0.0f, acc3 = 0.0f;
    int buf = 0, ph = 0;
    long long scur = s0;
    for (long long it = 0; it < niter; ++it) {
        mbar_wait(mb[buf], (unsigned)ph);

        // 8 rows/thread in two 4-row groups, each 48B-stride (conflict-free
        // LDS.128): group A = rows [4t, 4t+3], group B = rows [256+4t, ...].
        const float4* P4 = (const float4*)&sh_p[buf][0];
        const float4* T4 = (const float4*)&sh_t[buf][0];
        const int4*   O4 = (const int4*)&sh_o[buf][0];
        int tid = threadIdx.x;

        float4 a0 = P4[3*tid+0], a1 = P4[3*tid+1], a2 = P4[3*tid+2];
        float4 b0 = T4[3*tid+0], b1 = T4[3*tid+1], b2 = T4[3*tid+2];
        int4   oA = O4[tid];
        float4 c0 = P4[192+3*tid+0], c1 = P4[192+3*tid+1], c2 = P4[192+3*tid+2];
        float4 d0 = T4[192+3*tid+0], d1 = T4[192+3*tid+1], d2 = T4[192+3*tid+2];
        int4   oB = O4[64+tid];

        acc0 += row_loss(a0.x, b0.x, a0.y, b0.y, a0.z, b0.z, oA.x);
        acc1 += row_loss(a0.w, b0.w, a1.x, b1.x, a1.y, b1.y, oA.y);
        acc2 += row_loss(a1.z, b1.z, a1.w, b1.w, a2.x, b2.x, oA.z);
        acc3 += row_loss(a2.y, b2.y, a2.z, b2.z, a2.w, b2.w, oA.w);
        acc0 += row_loss(c0.x, d0.x, c0.y, d0.y, c0.z, d0.z, oB.x);
        acc1 += row_loss(c0.w, d0.w, c1.x, d1.x, c1.y, d1.y, oB.y);
        acc2 += row_loss(c1.z, d1.z, c1.w, d1.w, c2.x, d2.x, oB.z);
        acc3 += row_loss(c2.y, d2.y, c2.z, d2.z, c2.w, d2.w, oB.w);

        __syncthreads();   // buffer fully consumed before refill

        long long sfill = scur + (long long)STAGES * G;
        if (threadIdx.x == 0 && it + STAGES < niter) {
            mbar_expect(mb[buf], ST_BYTES);
            bulk_cp((unsigned)__cvta_generic_to_shared(&sh_p[buf][0]),
                    pred_b + sfill * (long long)PT_BYTES, PT_BYTES, mb[buf]);
            bulk_cp((unsigned)__cvta_generic_to_shared(&sh_t[buf][0]),
                    true_b + sfill * (long long)PT_BYTES, PT_BYTES, mb[buf]);
            bulk_cp((unsigned)__cvta_generic_to_shared(&sh_o[buf][0]),
                    ot_b + sfill * (long long)OT_BYTES, OT_BYTES, mb[buf]);
        }
        scur += G;
        if (++buf == STAGES) { buf = 0; ph ^= 1; }
    }

    // tail rows (B % ROWS == 0 for this dataset; kept for generality)
    if (blockIdx.x == 0 && threadIdx.x == 0 && n_tail > 0) {
        long long base = NST * ROWS;
        for (long long r = base; r < base + n_tail; r++)
            acc0 += row_loss(pred[3*r+0], truep[3*r+0],
                             pred[3*r+1], truep[3*r+1],
                             pred[3*r+2], truep[3*r+2], ot[r]);
    }

    // warp + block reduce (2 warps)
    float v = (acc0 + acc1) + (acc2 + acc3);
    #pragma unroll
    for (int o = 16; o > 0; o >>= 1)
        v += __shfl_down_sync(0xFFFFFFFFu, v, o);

    int lane = threadIdx.x & 31, wid = threadIdx.x >> 5;
    if (lane == 0) shred[wid] = v;
    __syncthreads();
    if (threadIdx.x == 0) {
        v = shred[0] + shred[1];
        atomicAdd(&g_slots[(blockIdx.x & 31) * 32], (double)v);
        __threadfence();
        unsigned int done = atomicAdd(&g_count, 1u);
        if (done == n_blocks - 1) {
            double total = 0.0;
            #pragma unroll
            for (int i = 0; i < 32; i++) {
                volatile double* sp = &g_slots[i * 32];
                total += *sp;
            }
            out[0] = (float)(total / (double)B);
            #pragma unroll
            for (int i = 0; i < 32; i++)
                g_slots[i * 32] = 0.0;
            g_count = 0u;
        }
    }
}

extern "C" void kernel_launch(void* const* d_in, const int* in_sizes, int n_in,
                              void* d_out, int out_size) {
    const float* pred = (const float*)d_in[0];
    const float* truep = (const float*)d_in[1];
    const int* ot = (const int*)d_in[2];
    float* out = (float*)d_out;

    long long B = (long long)in_sizes[2];   // rows
    long long NST = B / ROWS;
    long long n_tail = B % ROWS;

    long long blocks = 1036;                // 148 SMs x 7 CTAs (smem-bound), one wave
    if (NST > 0 && blocks > NST) blocks = NST;
    if (blocks < 1) blocks = 1;

    k_loss<<<(unsigned)blocks, THREADS>>>(
        (const char*)pred, (const char*)truep, (const char*)ot,
        pred, truep, ot, out, NST, n_tail, B, (unsigned)blocks);
}

// round 16
// speedup vs baseline: 1.0507x; 1.0507x over previous
#include <cuda_runtime.h>
#include <cuda_fp16.h>
#include <math.h>
#include <stdint.h>

// Scratch (no allocations). Zero-initialized; last block resets for replay.
static __device__ double g_slots[32 * 32];
static __device__ unsigned int g_count;

#define LOG2_1P1 0.13750352374993502f   // log2(1.1)
#define BIGC     1.099511627776e12f     // 2^40 (exact power of two)

#define ROWS    512                      // rows per pipeline stage
#define THREADS 128
#define STAGES  3

__device__ __forceinline__ float ex2f(float x) {
    float r; asm("ex2.approx.f32 %0, %1;" : "=f"(r) : "f"(x)); return r;
}
__device__ __forceinline__ float rcpf(float x) {
    float r; asm("rcp.approx.f32 %0, %1;" : "=f"(r) : "f"(x)); return r;
}

// |cnt(p) - cnt(t)| over 5 thresholds, computed pairwise in fp16.
// One pack, 5 HSET2 (both values per compare), 4 HADD2, then a single
// cross-half abs-diff extraction (PRMT swap + HSUB2 + mask + one F2F).
__device__ __forceinline__ float cnt_absdiff(float p, float t,
                                             __half2 h0, __half2 h1,
                                             __half2 h2, __half2 h3,
                                             __half2 h4) {
    __half2 x = __floats2half2_rn(p, t);          // lo = p, hi = t
    __half2 c = __hge2(x, h0);
    c = __hadd2(c, __hge2(x, h1));
    c = __hadd2(c, __hge2(x, h2));
    c = __hadd2(c, __hge2(x, h3));
    c = __hadd2(c, __hge2(x, h4));
    uint32_t cu = *reinterpret_cast<uint32_t*>(&c);
    uint32_t sw = __byte_perm(cu, 0, 0x1032);      // swap halves
    __half2 swh = *reinterpret_cast<__half2*>(&sw);
    __half2 d = __hsub2(c, swh);                   // lo = cnt_p - cnt_t
    uint32_t du = (*reinterpret_cast<uint32_t*>(&d)) & 0x00007fffu;  // |lo|
    __half dl = *reinterpret_cast<__half*>(&du);
    return __half2float(dl);                       // exact small integer
}

// total weight (1 + w_mid), predicate-free closed form (exact f32):
//   min(sat(t*inv_a), sat(c2 - t*inv_cb)) + min(2^(1 - t/d), 1) + [p<0]
__device__ __forceinline__ float wmid1(float p, float t,
                                       float inv_a, float inv_cb, float c2,
                                       float inv_d) {
    float u = __saturatef(t * inv_a);
    float v = __saturatef(fmaf(t, -inv_cb, c2));
    float wlow = fminf(u, v);
    float e2 = ex2f(fmaf(t, -inv_d, 1.0f));
    float pneg = __saturatef(p * -BIGC);
    return wlow + fminf(e2, 1.0f) + pneg;
}

__device__ __forceinline__ float row_loss(float ph, float th,
                                          float pc, float tc,
                                          float pn, float tn,
                                          int ot) {
    // fp16 threshold pairs (same value both halves)
    const __half2 H0 = __float2half2_rn(150.f),  H1 = __float2half2_rn(500.f),
                  H2 = __float2half2_rn(1000.f), H3 = __float2half2_rn(1800.f),
                  H4 = __float2half2_rn(2600.f);
    const __half2 C0 = __float2half2_rn(22.f), C1 = __float2half2_rn(35.f),
                  C2 = __float2half2_rn(45.f), C3 = __float2half2_rn(55.f),
                  C4 = __float2half2_rn(65.f);
    const __half2 N0 = __float2half2_rn(0.2f), N1 = __float2half2_rn(0.5f),
                  N2 = __float2half2_rn(1.0f), N3 = __float2half2_rn(1.5f),
                  N4 = __float2half2_rn(2.0f);

    float dd, wcls, W, s;

    // ---- head: a=80 b=1500 c=1750 d=2000
    dd = cnt_absdiff(ph, th, H0, H1, H2, H3, H4);
    wcls = ex2f(dd * LOG2_1P1);
    W = wmid1(ph, th, 1.0f/80.f, 1.0f/250.f, 7.0f, 1.0f/2000.f);
    s = fabsf(ph - th) * (wcls * W);

    // ---- chest: thr {22..65}*cs == x/cs vs fixed thr; a=10 b=75 c=85 d=100
    float cs = fmaf((float)ot, 0.1f, 0.8f);
    float ics = rcpf(cs);
    dd = cnt_absdiff(pc * ics, tc * ics, C0, C1, C2, C3, C4);
    wcls = ex2f(dd * LOG2_1P1);
    W = wmid1(pc, tc, 1.0f/10.f, 1.0f/10.f, 8.5f, 1.0f/100.f);
    s = fmaf(fabsf(pc - tc), wcls * W, s);

    // ---- neck: a=0.15 b=1.5 c=1.7 d=1.9
    dd = cnt_absdiff(pn, tn, N0, N1, N2, N3, N4);
    wcls = ex2f(dd * LOG2_1P1);
    W = wmid1(pn, tn, 1.0f/0.15f, 5.0f, 8.5f, 1.0f/1.9f);
    s = fmaf(fabsf(pn - tn), wcls * W, s);

    return s;
}

__device__ __forceinline__ void bulk_cp(unsigned dst, const char* src,
                                        unsigned bytes, unsigned mb) {
    asm volatile(
        "cp.async.bulk.shared::cta.global.mbarrier::complete_tx::bytes "
        "[%0], [%1], %2, [%3];"
        :: "r"(dst), "l"(src), "r"(bytes), "r"(mb) : "memory");
}
__device__ __forceinline__ void mbar_expect(unsigned mb, unsigned bytes) {
    asm volatile("mbarrier.arrive.expect_tx.shared.b64 _, [%0], %1;"
                 :: "r"(mb), "r"(bytes) : "memory");
}
__device__ __forceinline__ void mbar_wait(unsigned mb, unsigned phase) {
    asm volatile(
        "{\n\t"
        ".reg .pred P;\n\t"
        "W%=:\n\t"
        "mbarrier.try_wait.parity.acquire.cta.shared::cta.b64 P, [%0], %1, 0x989680;\n\t"
        "@!P bra W%=;\n\t"
        "}"
        :: "r"(mb), "r"(phase) : "memory");
}

// 3-stage bulk-copy ring (R12 config — best measured machine structure);
// classification counts in paired fp16, everything else exact f32.
__global__ void __launch_bounds__(THREADS)
k_loss(const char* __restrict__ pred_b, const char* __restrict__ true_b,
       const char* __restrict__ ot_b,
       const float* __restrict__ pred, const float* __restrict__ truep,
       const int* __restrict__ ot,
       float* __restrict__ out,
       long long NST, long long n_tail, long long B, unsigned int n_blocks) {
    __shared__ alignas(16) float sh_p[STAGES][ROWS * 3];
    __shared__ alignas(16) float sh_t[STAGES][ROWS * 3];
    __shared__ alignas(16) int   sh_o[STAGES][ROWS];
    __shared__ alignas(8) unsigned long long mbar_store[STAGES];
    __shared__ float shred[4];

    unsigned mb[STAGES];
    #pragma unroll
    for (int i = 0; i < STAGES; i++)
        mb[i] = (unsigned)__cvta_generic_to_shared(&mbar_store[i]);

    if (threadIdx.x == 0) {
        #pragma unroll
        for (int i = 0; i < STAGES; i++)
            asm volatile("mbarrier.init.shared.b64 [%0], 1;" :: "r"(mb[i]) : "memory");
    }
    __syncthreads();

    const long long G = gridDim.x;
    long long s0 = blockIdx.x;
    const long long niter = (s0 < NST) ? ((NST - 1 - s0) / G + 1) : 0;

    const unsigned PT_BYTES = ROWS * 12u;                 // 6144
    const unsigned OT_BYTES = ROWS * 4u;                  // 2048
    const unsigned ST_BYTES = 2u * PT_BYTES + OT_BYTES;   // 14336

    // prologue: fill all stages
    if (threadIdx.x == 0) {
        #pragma unroll
        for (int k = 0; k < STAGES; k++) {
            if (k < niter) {
                long long st_ = s0 + (long long)k * G;
                mbar_expect(mb[k], ST_BYTES);
                bulk_cp((unsigned)__cvta_generic_to_shared(&sh_p[k][0]),
                        pred_b + st_ * (long long)PT_BYTES, PT_BYTES, mb[k]);
                bulk_cp((unsigned)__cvta_generic_to_shared(&sh_t[k][0]),
                        true_b + st_ * (long long)PT_BYTES, PT_BYTES, mb[k]);
                bulk_cp((unsigned)__cvta_generic_to_shared(&sh_o[k][0]),
                        ot_b + st_ * (long long)OT_BYTES, OT_BYTES, mb[k]);
            }
        }
    }

    float acc0 = 0.0f, acc1 = 0.0f, acc2 = 0.0f, acc3 = 0.0f;
    int buf = 0, ph = 0;
    long long scur = s0;
    for (long long it = 0; it < niter; ++it) {
        mbar_wait(mb[buf], (unsigned)ph);

        // conflict-free vector reads: 3x LDS.128 pred, 3x true, 1x int4 ot
        const float4* P4 = (const float4*)&sh_p[buf][0];
        const float4* T4 = (const float4*)&sh_t[buf][0];
        const int4*   O4 = (const int4*)&sh_o[buf][0];
        int tid = threadIdx.x;
        float4 p0 = P4[3*tid+0], p1 = P4[3*tid+1], p2 = P4[3*tid+2];
        float4 t0 = T4[3*tid+0], t1 = T4[3*tid+1], t2 = T4[3*tid+2];
        int4   o  = O4[tid];

        acc0 += row_loss(p0.x, t0.x, p0.y, t0.y, p0.z, t0.z, o.x);
        acc1 += row_loss(p0.w, t0.w, p1.x, t1.x, p1.y, t1.y, o.y);
        acc2 += row_loss(p1.z, t1.z, p1.w, t1.w, p2.x, t2.x, o.z);
        acc3 += row_loss(p2.y, t2.y, p2.z, t2.z, p2.w, t2.w, o.w);

        __syncthreads();   // buffer fully consumed before refill

        long long sfill = scur + (long long)STAGES * G;
        if (threadIdx.x == 0 && it + STAGES < niter) {
            mbar_expect(mb[buf], ST_BYTES);
            bulk_cp((unsigned)__cvta_generic_to_shared(&sh_p[buf][0]),
                    pred_b + sfill * (long long)PT_BYTES, PT_BYTES, mb[buf]);
            bulk_cp((unsigned)__cvta_generic_to_shared(&sh_t[buf][0]),
                    true_b + sfill * (long long)PT_BYTES, PT_BYTES, mb[buf]);
            bulk_cp((unsigned)__cvta_generic_to_shared(&sh_o[buf][0]),
                    ot_b + sfill * (long long)OT_BYTES, OT_BYTES, mb[buf]);
        }
        scur += G;
        if (++buf == STAGES) { buf = 0; ph ^= 1; }
    }

    // tail rows (B % ROWS), one thread of block 0 via global loads
    if (blockIdx.x == 0 && threadIdx.x == 0 && n_tail > 0) {
        long long base = NST * ROWS;
        for (long long r = base; r < base + n_tail; r++)
            acc0 += row_loss(pred[3*r+0], truep[3*r+0],
                             pred[3*r+1], truep[3*r+1],
                             pred[3*r+2], truep[3*r+2], ot[r]);
    }

    // warp + block reduce
    float v = (acc0 + acc1) + (acc2 + acc3);
    #pragma unroll
    for (int o = 16; o > 0; o >>= 1)
        v += __shfl_down_sync(0xFFFFFFFFu, v, o);

    int lane = threadIdx.x & 31, wid = threadIdx.x >> 5;
    if (lane == 0) shred[wid] = v;
    __syncthreads();
    if (wid == 0) {
        v = (lane < 4) ? shred[lane] : 0.0f;
        #pragma unroll
        for (int o = 2; o > 0; o >>= 1)
            v += __shfl_down_sync(0xFFFFFFFFu, v, o);
        if (lane == 0) {
            atomicAdd(&g_slots[(blockIdx.x & 31) * 32], (double)v);
            __threadfence();
            unsigned int done = atomicAdd(&g_count, 1u);
            if (done == n_blocks - 1) {
                double total = 0.0;
                #pragma unroll
                for (int i = 0; i < 32; i++) {
                    volatile double* sp = &g_slots[i * 32];
                    total += *sp;
                }
                out[0] = (float)(total / (double)B);
                #pragma unroll
                for (int i = 0; i < 32; i++)
                    g_slots[i * 32] = 0.0;
                g_count = 0u;
            }
        }
    }
}

extern "C" void kernel_launch(void* const* d_in, const int* in_sizes, int n_in,
                              void* d_out, int out_size) {
    const float* pred = (const float*)d_in[0];
    const float* truep = (const float*)d_in[1];
    const int* ot = (const int*)d_in[2];
    float* out = (float*)d_out;

    long long B = (long long)in_sizes[2];   // rows
    long long NST = B / ROWS;
    long long n_tail = B % ROWS;

    long long blocks = 592;                 // 148 SMs x 4 CTAs, one wave
    if (NST > 0 && blocks > NST) blocks = NST;
    if (blocks < 1) blocks = 1;

    k_loss<<<(unsigned)blocks, THREADS>>>(
        (const char*)pred, (const char*)truep, (const char*)ot,
        pred, truep, ot, out, NST, n_tail, B, (unsigned)blocks);
}